// round 1
// baseline (speedup 1.0000x reference)
#include <cuda_runtime.h>
#include <math.h>

// Problem constants (fixed by reference setup_inputs)
#define BB     8
#define NFULL  8192
#define NPART  2048
#define DLAT   512
#define EPSV   1e-12f

// Scratch: per-point min squared distances (clamped), combined via atomicMin.
__device__ float g_pf[BB * NFULL];    // pred  -> full
__device__ float g_fp[BB * NFULL];    // full  -> pred
__device__ float g_part[BB * NPART];  // partial -> pred

constexpr int THREADS = 256;
constexpr int Q       = 4;               // queries per thread
constexpr int QPB     = THREADS * Q;     // 1024 queries per block
constexpr int CHUNK   = 2048;            // ref points per block tile (32KB smem)

// ---------------------------------------------------------------------------
// Init mins to +inf (as float; bit pattern 0x7f800000 works for uint atomicMin
// since all stored values are positive)
// ---------------------------------------------------------------------------
__global__ void init_min_kernel(float* pf, float* fp, float* pp) {
    int i = blockIdx.x * blockDim.x + threadIdx.x;
    const float INF = __int_as_float(0x7f800000);
    if (i < BB * NFULL) { pf[i] = INF; fp[i] = INF; }
    if (i < BB * NPART) { pp[i] = INF; }
}

// ---------------------------------------------------------------------------
// Row-min kernel: for each query point, min over a chunk of ref points of
// squared distance (expansion form q2 + r2 - 2*dot, matching reference).
// grid = (Nq/QPB, Nr/CHUNK, B)
// ---------------------------------------------------------------------------
__global__ __launch_bounds__(THREADS)
void rowmin_kernel(const float* __restrict__ q, const float* __restrict__ r,
                   float* __restrict__ outmin, int Nq, int Nr) {
    __shared__ float4 tile[CHUNK];

    const int b     = blockIdx.z;
    const int qbase = blockIdx.x * QPB;
    const int rbase = blockIdx.y * CHUNK;
    const float* qb = q + (size_t)b * Nq * 3;
    const float* rb = r + (size_t)b * Nr * 3;

    // Cooperative tile load: (x, y, z, r2)
    for (int j = threadIdx.x; j < CHUNK; j += THREADS) {
        int rj = rbase + j;
        float x = rb[rj * 3 + 0];
        float y = rb[rj * 3 + 1];
        float z = rb[rj * 3 + 2];
        tile[j] = make_float4(x, y, z, x * x + y * y + z * z);
    }
    __syncthreads();

    float qx[Q], qy[Q], qz[Q], q2[Q], m[Q];
#pragma unroll
    for (int k = 0; k < Q; k++) {
        int qi = qbase + threadIdx.x + k * THREADS;
        float x = qb[qi * 3 + 0];
        float y = qb[qi * 3 + 1];
        float z = qb[qi * 3 + 2];
        qx[k] = x; qy[k] = y; qz[k] = z;
        q2[k] = x * x + y * y + z * z;
        m[k]  = __int_as_float(0x7f800000);
    }

#pragma unroll 4
    for (int j = 0; j < CHUNK; j++) {
        float4 rf = tile[j];
#pragma unroll
        for (int k = 0; k < Q; k++) {
            float dot = qx[k] * rf.x;
            dot = fmaf(qy[k], rf.y, dot);
            dot = fmaf(qz[k], rf.z, dot);
            float t  = q2[k] + rf.w;
            float sq = fmaf(dot, -2.0f, t);   // q2 + r2 - 2*dot
            m[k] = fminf(m[k], sq);
        }
    }

    // Clamp (monotone w.r.t. min across chunks), combine via atomicMin on bits.
#pragma unroll
    for (int k = 0; k < Q; k++) {
        int qi  = qbase + threadIdx.x + k * THREADS;
        float v = fmaxf(m[k], EPSV);
        atomicMin((unsigned int*)&outmin[(size_t)b * Nq + qi], __float_as_uint(v));
    }
}

// ---------------------------------------------------------------------------
// Final reduce: sqrt + means + KL + weighted total. Single block.
// out = (total, cd, kl, fidel)
// ---------------------------------------------------------------------------
__global__ void reduce_kernel(const float* __restrict__ pf,
                              const float* __restrict__ fp,
                              const float* __restrict__ pp,
                              const float* __restrict__ mu,
                              const float* __restrict__ lv,
                              float* __restrict__ out) {
    const int tid = threadIdx.x;
    const int nt  = blockDim.x;

    float s_pf = 0.f, s_fp = 0.f, s_pp = 0.f, s_kl = 0.f;
    for (int i = tid; i < BB * NFULL; i += nt) {
        s_pf += sqrtf(pf[i]);
        s_fp += sqrtf(fp[i]);
    }
    for (int i = tid; i < BB * NPART; i += nt) s_pp += sqrtf(pp[i]);
    for (int i = tid; i < BB * DLAT; i += nt) {
        float m = mu[i], l = lv[i];
        s_kl += 1.0f + l - m * m - expf(l);
    }

    // Warp reduce then block reduce (4 sums)
    __shared__ float sh[4][32];
#pragma unroll
    for (int off = 16; off > 0; off >>= 1) {
        s_pf += __shfl_down_sync(0xffffffffu, s_pf, off);
        s_fp += __shfl_down_sync(0xffffffffu, s_fp, off);
        s_pp += __shfl_down_sync(0xffffffffu, s_pp, off);
        s_kl += __shfl_down_sync(0xffffffffu, s_kl, off);
    }
    int wid = tid >> 5, lid = tid & 31;
    if (lid == 0) { sh[0][wid] = s_pf; sh[1][wid] = s_fp; sh[2][wid] = s_pp; sh[3][wid] = s_kl; }
    __syncthreads();

    if (wid == 0) {
        int nwarps = nt >> 5;
        float a = (lid < nwarps) ? sh[0][lid] : 0.f;
        float b = (lid < nwarps) ? sh[1][lid] : 0.f;
        float c = (lid < nwarps) ? sh[2][lid] : 0.f;
        float d = (lid < nwarps) ? sh[3][lid] : 0.f;
#pragma unroll
        for (int off = 16; off > 0; off >>= 1) {
            a += __shfl_down_sync(0xffffffffu, a, off);
            b += __shfl_down_sync(0xffffffffu, b, off);
            c += __shfl_down_sync(0xffffffffu, c, off);
            d += __shfl_down_sync(0xffffffffu, d, off);
        }
        if (lid == 0) {
            float inv_nf = 1.0f / (float)(BB * NFULL);
            float cd  = 0.5f * (a + b) * inv_nf;
            float fid = c / (float)(BB * NPART);
            float kl  = -0.5f * d / (float)BB;
            float total = 1.0f * cd + 0.01f * kl + 0.5f * fid;
            out[0] = total;
            out[1] = cd;
            out[2] = kl;
            out[3] = fid;
        }
    }
}

// ---------------------------------------------------------------------------
// Launch
// ---------------------------------------------------------------------------
extern "C" void kernel_launch(void* const* d_in, const int* in_sizes, int n_in,
                              void* d_out, int out_size) {
    const float* pred    = (const float*)d_in[0];  // [8,8192,3]
    const float* full    = (const float*)d_in[1];  // [8,8192,3]
    const float* partial = (const float*)d_in[2];  // [8,2048,3]
    const float* mu      = (const float*)d_in[3];  // [8,512]
    const float* logvar  = (const float*)d_in[4];  // [8,512]
    float* out = (float*)d_out;

    float *pf, *fp, *pp;
    cudaGetSymbolAddress((void**)&pf, g_pf);
    cudaGetSymbolAddress((void**)&fp, g_fp);
    cudaGetSymbolAddress((void**)&pp, g_part);

    // 1) init mins
    {
        int n = BB * NFULL;
        init_min_kernel<<<(n + THREADS - 1) / THREADS, THREADS>>>(pf, fp, pp);
    }

    // 2) chamfer pred->full
    {
        dim3 grid(NFULL / QPB, NFULL / CHUNK, BB);
        rowmin_kernel<<<grid, THREADS>>>(pred, full, pf, NFULL, NFULL);
    }
    // 3) chamfer full->pred
    {
        dim3 grid(NFULL / QPB, NFULL / CHUNK, BB);
        rowmin_kernel<<<grid, THREADS>>>(full, pred, fp, NFULL, NFULL);
    }
    // 4) fidelity partial->pred
    {
        dim3 grid(NPART / QPB, NFULL / CHUNK, BB);
        rowmin_kernel<<<grid, THREADS>>>(partial, pred, pp, NPART, NFULL);
    }

    // 5) final reduce
    reduce_kernel<<<1, 1024>>>(pf, fp, pp, mu, logvar, out);
}

// round 2
// speedup vs baseline: 1.7063x; 1.7063x over previous
#include <cuda_runtime.h>
#include <math.h>

#define BB     8
#define NFULL  8192
#define NPART  2048
#define DLAT   512
#define EPSV   1e-12f

__device__ float g_pf[BB * NFULL];
__device__ float g_fp[BB * NFULL];
__device__ float g_part[BB * NPART];

constexpr int THREADS = 256;
constexpr int Q       = 4;                // queries per thread
constexpr int QPB     = THREADS * Q;      // 1024
constexpr int CHUNK   = 2048;             // ref points per tile
constexpr int CH2     = CHUNK / 2;        // packed pairs per tile

typedef unsigned long long u64;

__device__ __forceinline__ u64 pack2(float lo, float hi) {
    u64 r; asm("mov.b64 %0, {%1, %2};" : "=l"(r) : "f"(lo), "f"(hi)); return r;
}
__device__ __forceinline__ void unpack2(u64 v, float& lo, float& hi) {
    asm("mov.b64 {%0, %1}, %2;" : "=f"(lo), "=f"(hi) : "l"(v));
}
__device__ __forceinline__ u64 ffma2(u64 a, u64 b, u64 c) {
    u64 d; asm("fma.rn.f32x2 %0, %1, %2, %3;" : "=l"(d) : "l"(a), "l"(b), "l"(c)); return d;
}

// ---------------------------------------------------------------------------
__global__ void init_min_kernel(float* pf, float* fp, float* pp) {
    int i = blockIdx.x * blockDim.x + threadIdx.x;
    const float INF = __int_as_float(0x7f800000);
    if (i < BB * NFULL) { pf[i] = INF; fp[i] = INF; }
    if (i < BB * NPART) { pp[i] = INF; }
}

// ---------------------------------------------------------------------------
// Fused row-min: one launch covers chamfer pred->full, full->pred, and
// fidelity partial->pred. For each query q: min_j( w_j - dot(q, r_j) ) with
// w = |r|^2/2, then sq = q^2 + 2*min. Packed f32x2 processes 2 refs/instr.
// ---------------------------------------------------------------------------
constexpr int RCHUNKS   = NFULL / CHUNK;            // 4
constexpr int CHAM_QT   = NFULL / QPB;              // 8
constexpr int FID_QT    = NPART / QPB;              // 2
constexpr int CHAM_BLKS = CHAM_QT * RCHUNKS * BB;   // 256
constexpr int FID_BLKS  = FID_QT * RCHUNKS * BB;    // 64
constexpr int TOT_BLKS  = 2 * CHAM_BLKS + FID_BLKS; // 576

__global__ __launch_bounds__(THREADS)
void fused_rowmin_kernel(const float* __restrict__ pred,
                         const float* __restrict__ full,
                         const float* __restrict__ partial,
                         float* __restrict__ pf,
                         float* __restrict__ fp,
                         float* __restrict__ pp) {
    __shared__ float4 tA[CH2];   // (x0, x1, y0, y1)
    __shared__ float4 tB[CH2];   // (z0, z1, w0, w1)

    // ---- decode task ----
    const float *q, *r;
    float* outmin;
    int Nq, qtiles, l = blockIdx.x;
    if (l < CHAM_BLKS) {
        q = pred; r = full; outmin = pf; Nq = NFULL; qtiles = CHAM_QT;
    } else if (l < 2 * CHAM_BLKS) {
        l -= CHAM_BLKS;
        q = full; r = pred; outmin = fp; Nq = NFULL; qtiles = CHAM_QT;
    } else {
        l -= 2 * CHAM_BLKS;
        q = partial; r = pred; outmin = pp; Nq = NPART; qtiles = FID_QT;
    }
    const int b  = l / (qtiles * RCHUNKS);
    const int rm = l % (qtiles * RCHUNKS);
    const int ck = rm / qtiles;
    const int qt = rm % qtiles;
    const int qbase = qt * QPB;
    const int rbase = ck * CHUNK;

    const float* qb = q + (size_t)b * Nq * 3;
    const float* rb = r + (size_t)b * NFULL * 3;

    // ---- cooperative packed tile load ----
    for (int j = threadIdx.x; j < CH2; j += THREADS) {
        int rj = rbase + 2 * j;
        float x0 = rb[rj * 3 + 0], y0 = rb[rj * 3 + 1], z0 = rb[rj * 3 + 2];
        float x1 = rb[rj * 3 + 3], y1 = rb[rj * 3 + 4], z1 = rb[rj * 3 + 5];
        float w0 = 0.5f * (x0 * x0 + y0 * y0 + z0 * z0);
        float w1 = 0.5f * (x1 * x1 + y1 * y1 + z1 * z1);
        tA[j] = make_float4(x0, x1, y0, y1);
        tB[j] = make_float4(z0, z1, w0, w1);
    }
    __syncthreads();

    // ---- per-thread queries (negated, broadcast-packed) ----
    u64 nqx[Q], nqy[Q], nqz[Q];
    float q2[Q], m0[Q], m1[Q];
#pragma unroll
    for (int k = 0; k < Q; k++) {
        int qi = qbase + threadIdx.x + k * THREADS;
        float x = qb[qi * 3 + 0];
        float y = qb[qi * 3 + 1];
        float z = qb[qi * 3 + 2];
        nqx[k] = pack2(-x, -x);
        nqy[k] = pack2(-y, -y);
        nqz[k] = pack2(-z, -z);
        q2[k]  = x * x + y * y + z * z;
        m0[k]  = __int_as_float(0x7f800000);
        m1[k]  = __int_as_float(0x7f800000);
    }

    // ---- main loop: 2 ref points per iteration ----
#pragma unroll 4
    for (int j = 0; j < CH2; j++) {
        float4 A = tA[j];
        float4 B = tB[j];
        u64 xp = pack2(A.x, A.y);
        u64 yp = pack2(A.z, A.w);
        u64 zp = pack2(B.x, B.y);
        u64 wp = pack2(B.z, B.w);
#pragma unroll
        for (int k = 0; k < Q; k++) {
            u64 v = ffma2(nqz[k], zp, wp);
            v = ffma2(nqy[k], yp, v);
            v = ffma2(nqx[k], xp, v);
            float v0, v1;
            unpack2(v, v0, v1);
            m0[k] = fminf(m0[k], v0);
            m1[k] = fminf(m1[k], v1);
        }
    }

    // ---- writeback: sq = q2 + 2*min, clamp, atomic min-combine ----
#pragma unroll
    for (int k = 0; k < Q; k++) {
        int qi   = qbase + threadIdx.x + k * THREADS;
        float mn = fminf(m0[k], m1[k]);
        float sq = fmaf(2.0f, mn, q2[k]);
        float v  = fmaxf(sq, EPSV);
        atomicMin((unsigned int*)&outmin[(size_t)b * Nq + qi], __float_as_uint(v));
    }
}

// ---------------------------------------------------------------------------
__global__ void reduce_kernel(const float* __restrict__ pf,
                              const float* __restrict__ fp,
                              const float* __restrict__ pp,
                              const float* __restrict__ mu,
                              const float* __restrict__ lv,
                              float* __restrict__ out) {
    const int tid = threadIdx.x;
    const int nt  = blockDim.x;

    float s_pf = 0.f, s_fp = 0.f, s_pp = 0.f, s_kl = 0.f;
    for (int i = tid; i < BB * NFULL; i += nt) {
        s_pf += sqrtf(pf[i]);
        s_fp += sqrtf(fp[i]);
    }
    for (int i = tid; i < BB * NPART; i += nt) s_pp += sqrtf(pp[i]);
    for (int i = tid; i < BB * DLAT; i += nt) {
        float m = mu[i], l = lv[i];
        s_kl += 1.0f + l - m * m - expf(l);
    }

    __shared__ float sh[4][32];
#pragma unroll
    for (int off = 16; off > 0; off >>= 1) {
        s_pf += __shfl_down_sync(0xffffffffu, s_pf, off);
        s_fp += __shfl_down_sync(0xffffffffu, s_fp, off);
        s_pp += __shfl_down_sync(0xffffffffu, s_pp, off);
        s_kl += __shfl_down_sync(0xffffffffu, s_kl, off);
    }
    int wid = tid >> 5, lid = tid & 31;
    if (lid == 0) { sh[0][wid] = s_pf; sh[1][wid] = s_fp; sh[2][wid] = s_pp; sh[3][wid] = s_kl; }
    __syncthreads();

    if (wid == 0) {
        int nwarps = nt >> 5;
        float a = (lid < nwarps) ? sh[0][lid] : 0.f;
        float b = (lid < nwarps) ? sh[1][lid] : 0.f;
        float c = (lid < nwarps) ? sh[2][lid] : 0.f;
        float d = (lid < nwarps) ? sh[3][lid] : 0.f;
#pragma unroll
        for (int off = 16; off > 0; off >>= 1) {
            a += __shfl_down_sync(0xffffffffu, a, off);
            b += __shfl_down_sync(0xffffffffu, b, off);
            c += __shfl_down_sync(0xffffffffu, c, off);
            d += __shfl_down_sync(0xffffffffu, d, off);
        }
        if (lid == 0) {
            float inv_nf = 1.0f / (float)(BB * NFULL);
            float cd  = 0.5f * (a + b) * inv_nf;
            float fid = c / (float)(BB * NPART);
            float kl  = -0.5f * d / (float)BB;
            float total = 1.0f * cd + 0.01f * kl + 0.5f * fid;
            out[0] = total;
            out[1] = cd;
            out[2] = kl;
            out[3] = fid;
        }
    }
}

// ---------------------------------------------------------------------------
extern "C" void kernel_launch(void* const* d_in, const int* in_sizes, int n_in,
                              void* d_out, int out_size) {
    const float* pred    = (const float*)d_in[0];
    const float* full    = (const float*)d_in[1];
    const float* partial = (const float*)d_in[2];
    const float* mu      = (const float*)d_in[3];
    const float* logvar  = (const float*)d_in[4];
    float* out = (float*)d_out;

    float *pf, *fp, *pp;
    cudaGetSymbolAddress((void**)&pf, g_pf);
    cudaGetSymbolAddress((void**)&fp, g_fp);
    cudaGetSymbolAddress((void**)&pp, g_part);

    {
        int n = BB * NFULL;
        init_min_kernel<<<(n + THREADS - 1) / THREADS, THREADS>>>(pf, fp, pp);
    }

    fused_rowmin_kernel<<<TOT_BLKS, THREADS>>>(pred, full, partial, pf, fp, pp);

    reduce_kernel<<<1, 1024>>>(pf, fp, pp, mu, logvar, out);
}